// round 5
// baseline (speedup 1.0000x reference)
#include <cuda_runtime.h>
#include <cuda_bf16.h>

// ---------------------------------------------------------------------------
// GAT 2-layer + softmax head. 5 kernels:
//  1) node1_hist : h1 = x@W1 (f32x2 FMA, smem-staged), alphas, fused histogram
//  2) scan_one   : single-block int4 scan of degrees -> g_off/g_cur,
//                  re-zeros g_deg, sets off[n]=E
//  3) scatter    : CSR column build
//  4) agg_mid    : warp-per-dst softmax-agg (8 edge-slots x 4-feature quads,
//                  float4 gathers) + fused (relu, @W2, alphas) epilogue
//  5) agg_out    : same agg + fused output head (relu, @Wout+bout, softmax)
// ---------------------------------------------------------------------------

#define NMAX   100000
#define EMAX   3400000
#define IN_DIM 512
#define HID    16

__device__ __align__(16) float g_h [NMAX * HID];
__device__ __align__(16) float g_h2[NMAX * HID];
__device__ float g_as [NMAX];
__device__ float g_ad [NMAX];
__device__ float g_as2[NMAX];
__device__ float g_ad2[NMAX];

__device__ __align__(16) int g_deg[NMAX];      // static-zero; re-zeroed by scan
__device__ __align__(16) int g_off[NMAX + 4];
__device__ __align__(16) int g_cur[NMAX];
__device__ int g_csr[EMAX];

// ---------------------------------------------------------------------------
// packed fp32x2 helpers (sm_100+)
__device__ __forceinline__ unsigned long long dup2(float v) {
    unsigned long long r;
    asm("mov.b64 %0, {%1, %1};" : "=l"(r) : "f"(v));
    return r;
}
__device__ __forceinline__ void fma2(unsigned long long& d,
                                     unsigned long long a, unsigned long long b) {
    asm("fma.rn.f32x2 %0, %1, %2, %0;" : "+l"(d) : "l"(a), "l"(b));
}
__device__ __forceinline__ float2 unpk(unsigned long long v) {
    float2 r;
    asm("mov.b64 {%0, %1}, %2;" : "=f"(r.x), "=f"(r.y) : "l"(v));
    return r;
}

// ---------------------------------------------------------------------------
// Kernel 1: node transform layer 1 + fused edge histogram.
// ---------------------------------------------------------------------------
#define N1T   128
#define N1N   256
#define KT    32
#define XSTR  33
#define SM_W   0
#define SM_AVS 8192
#define SM_AVD 8208
#define SM_XS  8224
#define SM_FLOATS (SM_XS + N1N * XSTR)

__global__ void __launch_bounds__(N1T)
node1_hist_kernel(const float* __restrict__ x, const float* __restrict__ W1,
                  const float* __restrict__ a_s, const float* __restrict__ a_d,
                  const int* __restrict__ ei, int n, int E)
{
    extern __shared__ float sm[];
    const int t = threadIdx.x;
    const int node0 = blockIdx.x * N1N;

    for (int j = t; j < IN_DIM * HID / 4; j += N1T)
        ((float4*)(sm + SM_W))[j] = ((const float4*)W1)[j];
    if (t < HID)              sm[SM_AVS + t] = a_s[t];
    else if (t < 2 * HID)     sm[SM_AVD + t - HID] = a_d[t - HID];

    unsigned long long acc0[8], acc1[8];
#pragma unroll
    for (int p = 0; p < 8; p++) { acc0[p] = 0ull; acc1[p] = 0ull; }

    const float4 zero4 = make_float4(0.f, 0.f, 0.f, 0.f);

#pragma unroll 1
    for (int kb = 0; kb < IN_DIM / KT; kb++) {
        __syncthreads();
#pragma unroll
        for (int i = 0; i < 16; i++) {
            int j   = t + N1T * i;
            int row = j >> 3;
            int c4  = j & 7;
            int nd  = node0 + row;
            float4 v = (nd < n)
                ? *(const float4*)(x + (size_t)nd * IN_DIM + kb * KT + c4 * 4)
                : zero4;
            float* dp = sm + SM_XS + row * XSTR + c4 * 4;
            dp[0] = v.x; dp[1] = v.y; dp[2] = v.z; dp[3] = v.w;
        }
        __syncthreads();

#pragma unroll 8
        for (int kk = 0; kk < KT; kk++) {
            int k = kb * KT + kk;
            const unsigned long long* wq =
                (const unsigned long long*)(sm + SM_W + k * HID);
            unsigned long long x0 = dup2(sm[SM_XS + t * XSTR + kk]);
            unsigned long long x1 = dup2(sm[SM_XS + (t + N1T) * XSTR + kk]);
#pragma unroll
            for (int p = 0; p < 8; p++) {
                unsigned long long w = wq[p];
                fma2(acc0[p], x0, w);
                fma2(acc1[p], x1, w);
            }
        }
    }

#pragma unroll
    for (int which = 0; which < 2; which++) {
        int node = node0 + t + which * N1T;
        if (node < n) {
            unsigned long long* ac = which ? acc1 : acc0;
            float h[HID];
#pragma unroll
            for (int p = 0; p < 8; p++) {
                float2 f = unpk(ac[p]);
                h[2 * p] = f.x; h[2 * p + 1] = f.y;
            }
            float as_v = 0.f, ad_v = 0.f;
#pragma unroll
            for (int c = 0; c < HID; c++) {
                as_v = fmaf(h[c], sm[SM_AVS + c], as_v);
                ad_v = fmaf(h[c], sm[SM_AVD + c], ad_v);
            }
            float4* hp = (float4*)(g_h + (size_t)node * HID);
            hp[0] = make_float4(h[0],  h[1],  h[2],  h[3]);
            hp[1] = make_float4(h[4],  h[5],  h[6],  h[7]);
            hp[2] = make_float4(h[8],  h[9],  h[10], h[11]);
            hp[3] = make_float4(h[12], h[13], h[14], h[15]);
            g_as[node] = as_v;
            g_ad[node] = ad_v;
        }
    }

    int gtid   = blockIdx.x * N1T + t;
    int stride = gridDim.x * N1T;
    for (int i = gtid; i < E; i += stride)
        atomicAdd(&g_deg[ei[E + i]], 1);
}

// ---------------------------------------------------------------------------
// Kernel 2: single-block scan. 1024 threads, int4 per thread per tile.
// Produces g_off (exclusive), g_cur (= g_off), re-zeros g_deg, off[n] = E.
// ---------------------------------------------------------------------------
__global__ void __launch_bounds__(1024)
scan_one_kernel(int n, int E)
{
    __shared__ int wsum[32];
    __shared__ int sTot;
    const int t = threadIdx.x;
    const int lane = t & 31, wid = t >> 5;

    int running = 0;
    int nTiles = (n + 4095) >> 12;

    for (int tile = 0; tile < nTiles; tile++) {
        int base = (tile << 12) + t * 4;
        int4 v = make_int4(0, 0, 0, 0);
        if (base + 3 < n)      v = *(const int4*)(g_deg + base);
        else if (base < n) {
            v.x = g_deg[base];
            if (base + 1 < n) v.y = g_deg[base + 1];
            if (base + 2 < n) v.z = g_deg[base + 2];
        }
        int s01  = v.x + v.y;
        int tsum = s01 + v.z + v.w;

        int incl = tsum;
#pragma unroll
        for (int o = 1; o < 32; o <<= 1) {
            int u = __shfl_up_sync(0xffffffffu, incl, o);
            if (lane >= o) incl += u;
        }
        if (lane == 31) wsum[wid] = incl;
        __syncthreads();
        if (wid == 0) {
            int w = wsum[lane];
            int wi = w;
#pragma unroll
            for (int o = 1; o < 32; o <<= 1) {
                int u = __shfl_up_sync(0xffffffffu, wi, o);
                if (lane >= o) wi += u;
            }
            wsum[lane] = wi - w;
            if (lane == 31) sTot = wi;
        }
        __syncthreads();

        int pre = running + wsum[wid] + (incl - tsum);
        if (base + 3 < n) {
            int4 o4 = make_int4(pre, pre + v.x, pre + s01, pre + s01 + v.z);
            *(int4*)(g_off + base) = o4;
            *(int4*)(g_cur + base) = o4;
            *(int4*)(g_deg + base) = make_int4(0, 0, 0, 0);
        } else if (base < n) {
            int o0 = pre, o1 = pre + v.x, o2 = pre + s01;
            g_off[base] = o0; g_cur[base] = o0; g_deg[base] = 0;
            if (base + 1 < n) { g_off[base+1] = o1; g_cur[base+1] = o1; g_deg[base+1] = 0; }
            if (base + 2 < n) { g_off[base+2] = o2; g_cur[base+2] = o2; g_deg[base+2] = 0; }
        }
        running += sTot;
        __syncthreads();
    }
    if (t == 0) g_off[n] = E;
}

// ---------------------------------------------------------------------------
// Kernel 3: CSR scatter
// ---------------------------------------------------------------------------
__global__ void __launch_bounds__(256)
scatter_kernel(const int* __restrict__ ei, int E)
{
    int i = blockIdx.x * blockDim.x + threadIdx.x;
    if (i < E) {
        int d = __ldg(ei + E + i);
        int pos = atomicAdd(&g_cur[d], 1);
        g_csr[pos] = __ldg(ei + i);
    }
}

// ---------------------------------------------------------------------------
// warp-per-dst aggregation core: 8 edge-slots x 4-feature quads.
// Quad q of slot s reads h[src_slot_s][q*4..q*4+3] as float4 (contiguous 64B
// per row across the quad). Returns per-lane facc4 (full slot-reduced) and
// fully reduced zacc on all lanes.
// ---------------------------------------------------------------------------
__device__ __forceinline__ void agg_core(
    int d, int lane, const float* __restrict__ hsrc,
    const float* __restrict__ asrc, float ad_d,
    float4& facc_o, float& zacc_o)
{
    const int begin = g_off[d];
    const int deg   = g_off[d + 1] - begin;
    const int nE    = deg + 1;
    const int slot  = lane >> 2;
    const int coff  = (lane & 3) << 2;

    float4 facc = make_float4(0.f, 0.f, 0.f, 0.f);
    float  zacc = 0.f;

    const int fullB = nE >> 5;
    for (int b = 0; b < fullB; b++) {
        int eidx = (b << 5) + lane;
        int s = (eidx < deg) ? __ldg(g_csr + begin + eidx) : d;
        float v = __ldg(asrc + s) + ad_d;
        v = (v > 0.f) ? v : 0.2f * v;
        float e = __expf(v);
        zacc += e;
#pragma unroll
        for (int j = 0; j < 4; j++) {
            int   sl = (j << 3) + slot;
            float e2 = __shfl_sync(0xffffffffu, e, sl);
            int   s2 = __shfl_sync(0xffffffffu, s, sl);
            float4 hv = *(const float4*)(hsrc + s2 * HID + coff);
            facc.x = fmaf(e2, hv.x, facc.x);
            facc.y = fmaf(e2, hv.y, facc.y);
            facc.z = fmaf(e2, hv.z, facc.z);
            facc.w = fmaf(e2, hv.w, facc.w);
        }
    }
    int b0 = fullB << 5;
    if (b0 < nE) {
        int eidx = b0 + lane;
        bool valid = eidx < nE;
        int s = (eidx < deg) ? __ldg(g_csr + begin + eidx) : d;
        float v = __ldg(asrc + s) + ad_d;
        v = (v > 0.f) ? v : 0.2f * v;
        float e = valid ? __expf(v) : 0.f;
        zacc += e;
        int jmax = (nE - b0 + 7) >> 3;
#pragma unroll 4
        for (int j = 0; j < jmax; j++) {
            int   sl = (j << 3) + slot;
            float e2 = __shfl_sync(0xffffffffu, e, sl);
            int   s2 = __shfl_sync(0xffffffffu, s, sl);
            float4 hv = *(const float4*)(hsrc + s2 * HID + coff);
            facc.x = fmaf(e2, hv.x, facc.x);
            facc.y = fmaf(e2, hv.y, facc.y);
            facc.z = fmaf(e2, hv.z, facc.z);
            facc.w = fmaf(e2, hv.w, facc.w);
        }
    }

    // reduce over slots (lane bits 2..4)
#pragma unroll
    for (int m = 4; m <= 16; m <<= 1) {
        facc.x += __shfl_xor_sync(0xffffffffu, facc.x, m);
        facc.y += __shfl_xor_sync(0xffffffffu, facc.y, m);
        facc.z += __shfl_xor_sync(0xffffffffu, facc.z, m);
        facc.w += __shfl_xor_sync(0xffffffffu, facc.w, m);
    }
#pragma unroll
    for (int m = 16; m > 0; m >>= 1)
        zacc += __shfl_xor_sync(0xffffffffu, zacc, m);

    facc_o = facc;
    zacc_o = zacc;
}

#define AGG_WARPS 8

// ---------------------------------------------------------------------------
// Kernel 4: layer-1 aggregation + fused node-mid epilogue
// ---------------------------------------------------------------------------
__global__ void __launch_bounds__(AGG_WARPS * 32)
agg_mid_kernel(const float* __restrict__ W2, const float* __restrict__ a_s,
               const float* __restrict__ a_d, const float* __restrict__ b, int n)
{
    __shared__ float Ws[HID * HID];
    __shared__ float avs[HID], avd[HID], bs[HID];
    __shared__ float hx[AGG_WARPS][HID];
    int t = threadIdx.x;
    if (t < HID * HID) Ws[t] = W2[t];
    if (t < HID) { avs[t] = a_s[t]; avd[t] = a_d[t]; bs[t] = b[t]; }
    __syncthreads();

    int w = t >> 5;
    int d = blockIdx.x * AGG_WARPS + w;
    if (d >= n) return;
    int lane = t & 31;
    int c    = lane & 15;

    float4 facc; float zacc;
    agg_core(d, lane, g_h, g_as, __ldg(&g_ad[d]), facc, zacc);

    // exchange: lanes 0..3 publish feature quads
    if (lane < 4) *(float4*)&hx[w][lane << 2] = facc;
    __syncwarp();
    float hin = fmaxf(fmaf(hx[w][c], 1.f / (zacc + 1e-16f), bs[c]), 0.f);

    float h2 = 0.f;
#pragma unroll
    for (int cc = 0; cc < HID; cc++) {
        float v = __shfl_sync(0xffffffffu, hin, cc);
        h2 = fmaf(v, Ws[cc * HID + c], h2);
    }
    float pa = h2 * avs[c];
    float pd = h2 * avd[c];
#pragma unroll
    for (int ofs = 8; ofs > 0; ofs >>= 1) {
        pa += __shfl_xor_sync(0xffffffffu, pa, ofs);
        pd += __shfl_xor_sync(0xffffffffu, pd, ofs);
    }
    if (lane < HID) g_h2[d * HID + lane] = h2;
    if (lane == 0) { g_as2[d] = pa; g_ad2[d] = pd; }
}

// ---------------------------------------------------------------------------
// Kernel 5: layer-2 aggregation + fused output head
// ---------------------------------------------------------------------------
__global__ void __launch_bounds__(AGG_WARPS * 32)
agg_out_kernel(const float* __restrict__ Wout, const float* __restrict__ bout,
               const float* __restrict__ b, float* __restrict__ out, int n)
{
    __shared__ float Ws[HID * HID];
    __shared__ float bos[HID], bs[HID];
    __shared__ float hx[AGG_WARPS][HID];
    int t = threadIdx.x;
    if (t < HID * HID) Ws[t] = Wout[t];
    if (t < HID) { bos[t] = bout[t]; bs[t] = b[t]; }
    __syncthreads();

    int w = t >> 5;
    int d = blockIdx.x * AGG_WARPS + w;
    if (d >= n) return;
    int lane = t & 31;
    int c    = lane & 15;

    float4 facc; float zacc;
    agg_core(d, lane, g_h2, g_as2, __ldg(&g_ad2[d]), facc, zacc);

    if (lane < 4) *(float4*)&hx[w][lane << 2] = facc;
    __syncwarp();
    float hin = fmaxf(fmaf(hx[w][c], 1.f / (zacc + 1e-16f), bs[c]), 0.f);

    float l = bos[c];
#pragma unroll
    for (int cc = 0; cc < HID; cc++) {
        float v = __shfl_sync(0xffffffffu, hin, cc);
        l = fmaf(v, Ws[cc * HID + c], l);
    }
    float m = l;
#pragma unroll
    for (int ofs = 8; ofs > 0; ofs >>= 1)
        m = fmaxf(m, __shfl_xor_sync(0xffffffffu, m, ofs));
    float e = __expf(l - m);
    float ssum = e;
#pragma unroll
    for (int ofs = 8; ofs > 0; ofs >>= 1)
        ssum += __shfl_xor_sync(0xffffffffu, ssum, ofs);

    if (lane < HID) out[(size_t)d * HID + lane] = e / ssum;
}

// ---------------------------------------------------------------------------
extern "C" void kernel_launch(void* const* d_in, const int* in_sizes, int n_in,
                              void* d_out, int out_size)
{
    const float* x    = (const float*)d_in[0];
    const float* W1   = (const float*)d_in[1];
    const float* as1  = (const float*)d_in[2];
    const float* ad1  = (const float*)d_in[3];
    const float* b1   = (const float*)d_in[4];
    const float* W2   = (const float*)d_in[5];
    const float* as2  = (const float*)d_in[6];
    const float* ad2  = (const float*)d_in[7];
    const float* b2   = (const float*)d_in[8];
    const float* Wout = (const float*)d_in[9];
    const float* bout = (const float*)d_in[10];
    const int*   ei   = (const int*)d_in[11];

    int n = in_sizes[0] / IN_DIM;
    int E = in_sizes[11] / 2;
    float* out = (float*)d_out;

    int n1Blocks   = (n + N1N - 1) / N1N;
    int edgeBlocks = (E + 255) / 256;
    int aggBlocks  = (n + AGG_WARPS - 1) / AGG_WARPS;
    size_t smBytes = SM_FLOATS * sizeof(float);

    cudaFuncSetAttribute(node1_hist_kernel,
                         cudaFuncAttributeMaxDynamicSharedMemorySize,
                         (int)smBytes);

    node1_hist_kernel<<<n1Blocks, N1T, smBytes>>>(x, W1, as1, ad1, ei, n, E);
    scan_one_kernel<<<1, 1024>>>(n, E);
    scatter_kernel<<<edgeBlocks, 256>>>(ei, E);
    agg_mid_kernel<<<aggBlocks, AGG_WARPS * 32>>>(W2, as2, ad2, b1, n);
    agg_out_kernel<<<aggBlocks, AGG_WARPS * 32>>>(Wout, bout, b2, out, n);
}

// round 6
// speedup vs baseline: 1.1936x; 1.1936x over previous
#include <cuda_runtime.h>
#include <cuda_bf16.h>

// ---------------------------------------------------------------------------
// GAT 2-layer + softmax head. 5 kernels:
//  1) node1_hist : h1 = x@W1 via cp.async double-buffered smem pipeline,
//                  f32x2-packed FMA, alphas, fused edge histogram
//  2) scan_one   : single-block int4 scan of degrees -> g_off/g_cur,
//                  re-zeros g_deg, sets off[n]=E
//  3) scatter    : CSR column build
//  4) agg_mid    : warp-per-dst softmax-agg (8 edge-slots x 4-feature quads)
//                  + fused (relu, @W2, alphas) epilogue
//  5) agg_out    : same agg + fused output head (relu, @Wout+bout, softmax)
// ---------------------------------------------------------------------------

#define NMAX   100000
#define EMAX   3400000
#define IN_DIM 512
#define HID    16

__device__ __align__(16) float g_h [NMAX * HID];
__device__ __align__(16) float g_h2[NMAX * HID];
__device__ float g_as [NMAX];
__device__ float g_ad [NMAX];
__device__ float g_as2[NMAX];
__device__ float g_ad2[NMAX];

__device__ __align__(16) int g_deg[NMAX];      // static-zero; re-zeroed by scan
__device__ __align__(16) int g_off[NMAX + 4];
__device__ __align__(16) int g_cur[NMAX];
__device__ int g_csr[EMAX];

// ---------------------------------------------------------------------------
// packed fp32x2 helpers (sm_100+)
__device__ __forceinline__ unsigned long long dup2(float v) {
    unsigned long long r;
    asm("mov.b64 %0, {%1, %1};" : "=l"(r) : "f"(v));
    return r;
}
__device__ __forceinline__ void fma2(unsigned long long& d,
                                     unsigned long long a, unsigned long long b) {
    asm("fma.rn.f32x2 %0, %1, %2, %0;" : "+l"(d) : "l"(a), "l"(b));
}
__device__ __forceinline__ float2 unpk(unsigned long long v) {
    float2 r;
    asm("mov.b64 {%0, %1}, %2;" : "=f"(r.x), "=f"(r.y) : "l"(v));
    return r;
}

// cp.async helpers
__device__ __forceinline__ void cp_async16(unsigned sm_addr, const void* g) {
    asm volatile("cp.async.cg.shared.global [%0], [%1], 16;"
                 :: "r"(sm_addr), "l"(g));
}
__device__ __forceinline__ void cp_commit() {
    asm volatile("cp.async.commit_group;");
}
__device__ __forceinline__ void cp_wait1() {
    asm volatile("cp.async.wait_group 1;");
}
__device__ __forceinline__ void cp_wait0() {
    asm volatile("cp.async.wait_group 0;");
}

// ---------------------------------------------------------------------------
// Kernel 1: node transform layer 1 (cp.async pipeline) + fused histogram.
// 256 threads = 256 nodes per block. 16 k-tiles of 32 cols.
// smem (floats): [W1: 8192][avs 16][avd 16][xs: 2 x 256 x 32 swizzled]
// ---------------------------------------------------------------------------
#define N1T   256
#define KT    32
#define NTILE (IN_DIM / KT)          // 16
#define SMF_W   0
#define SMF_AVS 8192
#define SMF_AVD 8208
#define SMF_XS  8224
#define SMF_TOT (SMF_XS + 2 * N1T * KT)   // 24608 floats = 98432 B

__global__ void __launch_bounds__(N1T)
node1_hist_kernel(const float* __restrict__ x, const float* __restrict__ W1,
                  const float* __restrict__ a_s, const float* __restrict__ a_d,
                  const int* __restrict__ ei, int n, int E)
{
    extern __shared__ float sm[];
    const int t = threadIdx.x;
    const int node0 = blockIdx.x * N1T;
    const unsigned smBase = (unsigned)__cvta_generic_to_shared(sm);

    // stage W1 + alphas
    for (int j = t; j < IN_DIM * HID / 4; j += N1T)
        ((float4*)(sm + SMF_W))[j] = ((const float4*)W1)[j];
    if (t < HID)            sm[SMF_AVS + t] = a_s[t];
    else if (t < 2 * HID)   sm[SMF_AVD + t - HID] = a_d[t - HID];
    __syncthreads();

    // prefetch lambda-ish macro: tile kb -> buffer b (8 chunks of 16B / thread)
    // chunk layout: row r, chunk c (16B) stored at r*128 + ((c ^ (r&7))<<4)
#define PREFETCH(kb, b) do {                                                  \
        int _kb = (kb);                                                       \
        unsigned _dstBase = smBase + (SMF_XS + (b) * N1T * KT) * 4;           \
        _Pragma("unroll")                                                     \
        for (int _i = 0; _i < 8; _i++) {                                      \
            int _idx = t + N1T * _i;          /* 0..2047 */                   \
            int _row = _idx >> 3;                                             \
            int _c   = _idx & 7;                                              \
            int _nd  = node0 + _row;                                          \
            if (_nd < n) {                                                    \
                unsigned _dst = _dstBase + _row * 128 +                       \
                                (((_c ^ (_row & 7))) << 4);                   \
                cp_async16(_dst, x + (size_t)_nd * IN_DIM + _kb * KT + _c*4); \
            }                                                                 \
        }                                                                     \
        cp_commit();                                                          \
    } while (0)

    unsigned long long acc[8];
#pragma unroll
    for (int p = 0; p < 8; p++) acc[p] = 0ull;

    PREFETCH(0, 0);
    PREFETCH(1, 1);

#pragma unroll 1
    for (int kb = 0; kb < NTILE; kb++) {
        if (kb == NTILE - 1) cp_wait0(); else cp_wait1();
        __syncthreads();

        // pull my row (32 floats) into registers: 8 swizzled LDS.128
        const int b = kb & 1;
        const float* xbuf = sm + SMF_XS + b * N1T * KT;
        float4 xr[8];
#pragma unroll
        for (int c = 0; c < 8; c++)
            xr[c] = *(const float4*)(xbuf + t * KT + ((c ^ (t & 7)) << 2));

        __syncthreads();                     // buffer free for next prefetch
        if (kb + 2 < NTILE) PREFETCH(kb + 2, b);

        // FMA: 32 k-steps, W rows from smem as 2x ulonglong2 (LDS.128 bcast)
#pragma unroll
        for (int c = 0; c < 8; c++) {
            float xv[4] = {xr[c].x, xr[c].y, xr[c].z, xr[c].w};
#pragma unroll
            for (int j = 0; j < 4; j++) {
                int k = kb * KT + c * 4 + j;
                const ulonglong2* wq =
                    (const ulonglong2*)(sm + SMF_W + k * HID);
                ulonglong2 wa = wq[0];
                ulonglong2 wb = wq[1];
                unsigned long long xd = dup2(xv[j]);
                fma2(acc[0], xd, wa.x);
                fma2(acc[1], xd, wa.y);
                fma2(acc[2], xd, wb.x);
                fma2(acc[3], xd, wb.y);
                const ulonglong2* wq2 =
                    (const ulonglong2*)(sm + SMF_W + k * HID + 8);
                ulonglong2 wc = wq2[0];
                ulonglong2 wd = wq2[1];
                fma2(acc[4], xd, wc.x);
                fma2(acc[5], xd, wc.y);
                fma2(acc[6], xd, wd.x);
                fma2(acc[7], xd, wd.y);
            }
        }
    }
#undef PREFETCH

    const int node = node0 + t;
    if (node < n) {
        float h[HID];
#pragma unroll
        for (int p = 0; p < 8; p++) {
            float2 f = unpk(acc[p]);
            h[2 * p] = f.x; h[2 * p + 1] = f.y;
        }
        float as_v = 0.f, ad_v = 0.f;
#pragma unroll
        for (int c = 0; c < HID; c++) {
            as_v = fmaf(h[c], sm[SMF_AVS + c], as_v);
            ad_v = fmaf(h[c], sm[SMF_AVD + c], ad_v);
        }
        float4* hp = (float4*)(g_h + (size_t)node * HID);
        hp[0] = make_float4(h[0],  h[1],  h[2],  h[3]);
        hp[1] = make_float4(h[4],  h[5],  h[6],  h[7]);
        hp[2] = make_float4(h[8],  h[9],  h[10], h[11]);
        hp[3] = make_float4(h[12], h[13], h[14], h[15]);
        g_as[node] = as_v;
        g_ad[node] = ad_v;
    }

    // fused histogram (g_deg zero on entry; re-zeroed by scan)
    int gtid   = blockIdx.x * N1T + t;
    int stride = gridDim.x * N1T;
    for (int i = gtid; i < E; i += stride)
        atomicAdd(&g_deg[ei[E + i]], 1);
}

// ---------------------------------------------------------------------------
// Kernel 2: single-block scan. 1024 threads, int4 per thread per tile.
// ---------------------------------------------------------------------------
__global__ void __launch_bounds__(1024)
scan_one_kernel(int n, int E)
{
    __shared__ int wsum[32];
    __shared__ int sTot;
    const int t = threadIdx.x;
    const int lane = t & 31, wid = t >> 5;

    int running = 0;
    int nTiles = (n + 4095) >> 12;

    for (int tile = 0; tile < nTiles; tile++) {
        int base = (tile << 12) + t * 4;
        int4 v = make_int4(0, 0, 0, 0);
        if (base + 3 < n)      v = *(const int4*)(g_deg + base);
        else if (base < n) {
            v.x = g_deg[base];
            if (base + 1 < n) v.y = g_deg[base + 1];
            if (base + 2 < n) v.z = g_deg[base + 2];
        }
        int s01  = v.x + v.y;
        int tsum = s01 + v.z + v.w;

        int incl = tsum;
#pragma unroll
        for (int o = 1; o < 32; o <<= 1) {
            int u = __shfl_up_sync(0xffffffffu, incl, o);
            if (lane >= o) incl += u;
        }
        if (lane == 31) wsum[wid] = incl;
        __syncthreads();
        if (wid == 0) {
            int w = wsum[lane];
            int wi = w;
#pragma unroll
            for (int o = 1; o < 32; o <<= 1) {
                int u = __shfl_up_sync(0xffffffffu, wi, o);
                if (lane >= o) wi += u;
            }
            wsum[lane] = wi - w;
            if (lane == 31) sTot = wi;
        }
        __syncthreads();

        int pre = running + wsum[wid] + (incl - tsum);
        if (base + 3 < n) {
            int4 o4 = make_int4(pre, pre + v.x, pre + s01, pre + s01 + v.z);
            *(int4*)(g_off + base) = o4;
            *(int4*)(g_cur + base) = o4;
            *(int4*)(g_deg + base) = make_int4(0, 0, 0, 0);
        } else if (base < n) {
            int o0 = pre, o1 = pre + v.x, o2 = pre + s01;
            g_off[base] = o0; g_cur[base] = o0; g_deg[base] = 0;
            if (base + 1 < n) { g_off[base+1] = o1; g_cur[base+1] = o1; g_deg[base+1] = 0; }
            if (base + 2 < n) { g_off[base+2] = o2; g_cur[base+2] = o2; g_deg[base+2] = 0; }
        }
        running += sTot;
        __syncthreads();
    }
    if (t == 0) g_off[n] = E;
}

// ---------------------------------------------------------------------------
// Kernel 3: CSR scatter
// ---------------------------------------------------------------------------
__global__ void __launch_bounds__(256)
scatter_kernel(const int* __restrict__ ei, int E)
{
    int i = blockIdx.x * blockDim.x + threadIdx.x;
    if (i < E) {
        int d = __ldg(ei + E + i);
        int pos = atomicAdd(&g_cur[d], 1);
        g_csr[pos] = __ldg(ei + i);
    }
}

// ---------------------------------------------------------------------------
// warp-per-dst aggregation core: 8 edge-slots x 4-feature quads.
// ---------------------------------------------------------------------------
__device__ __forceinline__ void agg_core(
    int d, int lane, const float* __restrict__ hsrc,
    const float* __restrict__ asrc, float ad_d,
    float4& facc_o, float& zacc_o)
{
    const int begin = g_off[d];
    const int deg   = g_off[d + 1] - begin;
    const int nE    = deg + 1;
    const int slot  = lane >> 2;
    const int coff  = (lane & 3) << 2;

    float4 facc = make_float4(0.f, 0.f, 0.f, 0.f);
    float  zacc = 0.f;

    const int fullB = nE >> 5;
    for (int b = 0; b < fullB; b++) {
        int eidx = (b << 5) + lane;
        int s = (eidx < deg) ? __ldg(g_csr + begin + eidx) : d;
        float v = __ldg(asrc + s) + ad_d;
        v = (v > 0.f) ? v : 0.2f * v;
        float e = __expf(v);
        zacc += e;
#pragma unroll
        for (int j = 0; j < 4; j++) {
            int   sl = (j << 3) + slot;
            float e2 = __shfl_sync(0xffffffffu, e, sl);
            int   s2 = __shfl_sync(0xffffffffu, s, sl);
            float4 hv = *(const float4*)(hsrc + s2 * HID + coff);
            facc.x = fmaf(e2, hv.x, facc.x);
            facc.y = fmaf(e2, hv.y, facc.y);
            facc.z = fmaf(e2, hv.z, facc.z);
            facc.w = fmaf(e2, hv.w, facc.w);
        }
    }
    int b0 = fullB << 5;
    if (b0 < nE) {
        int eidx = b0 + lane;
        bool valid = eidx < nE;
        int s = (eidx < deg) ? __ldg(g_csr + begin + eidx) : d;
        float v = __ldg(asrc + s) + ad_d;
        v = (v > 0.f) ? v : 0.2f * v;
        float e = valid ? __expf(v) : 0.f;
        zacc += e;
        int jmax = (nE - b0 + 7) >> 3;
#pragma unroll 4
        for (int j = 0; j < jmax; j++) {
            int   sl = (j << 3) + slot;
            float e2 = __shfl_sync(0xffffffffu, e, sl);
            int   s2 = __shfl_sync(0xffffffffu, s, sl);
            float4 hv = *(const float4*)(hsrc + s2 * HID + coff);
            facc.x = fmaf(e2, hv.x, facc.x);
            facc.y = fmaf(e2, hv.y, facc.y);
            facc.z = fmaf(e2, hv.z, facc.z);
            facc.w = fmaf(e2, hv.w, facc.w);
        }
    }

#pragma unroll
    for (int m = 4; m <= 16; m <<= 1) {
        facc.x += __shfl_xor_sync(0xffffffffu, facc.x, m);
        facc.y += __shfl_xor_sync(0xffffffffu, facc.y, m);
        facc.z += __shfl_xor_sync(0xffffffffu, facc.z, m);
        facc.w += __shfl_xor_sync(0xffffffffu, facc.w, m);
    }
#pragma unroll
    for (int m = 16; m > 0; m >>= 1)
        zacc += __shfl_xor_sync(0xffffffffu, zacc, m);

    facc_o = facc;
    zacc_o = zacc;
}

#define AGG_WARPS 8

// ---------------------------------------------------------------------------
// Kernel 4: layer-1 aggregation + fused node-mid epilogue
// ---------------------------------------------------------------------------
__global__ void __launch_bounds__(AGG_WARPS * 32)
agg_mid_kernel(const float* __restrict__ W2, const float* __restrict__ a_s,
               const float* __restrict__ a_d, const float* __restrict__ b, int n)
{
    __shared__ float Ws[HID * HID];
    __shared__ float avs[HID], avd[HID], bs[HID];
    __shared__ float hx[AGG_WARPS][HID];
    int t = threadIdx.x;
    if (t < HID * HID) Ws[t] = W2[t];
    if (t < HID) { avs[t] = a_s[t]; avd[t] = a_d[t]; bs[t] = b[t]; }
    __syncthreads();

    int w = t >> 5;
    int d = blockIdx.x * AGG_WARPS + w;
    if (d >= n) return;
    int lane = t & 31;
    int c    = lane & 15;

    float4 facc; float zacc;
    agg_core(d, lane, g_h, g_as, __ldg(&g_ad[d]), facc, zacc);

    if (lane < 4) *(float4*)&hx[w][lane << 2] = facc;
    __syncwarp();
    float hin = fmaxf(fmaf(hx[w][c], 1.f / (zacc + 1e-16f), bs[c]), 0.f);

    float h2 = 0.f;
#pragma unroll
    for (int cc = 0; cc < HID; cc++) {
        float v = __shfl_sync(0xffffffffu, hin, cc);
        h2 = fmaf(v, Ws[cc * HID + c], h2);
    }
    float pa = h2 * avs[c];
    float pd = h2 * avd[c];
#pragma unroll
    for (int ofs = 8; ofs > 0; ofs >>= 1) {
        pa += __shfl_xor_sync(0xffffffffu, pa, ofs);
        pd += __shfl_xor_sync(0xffffffffu, pd, ofs);
    }
    if (lane < HID) g_h2[d * HID + lane] = h2;
    if (lane == 0) { g_as2[d] = pa; g_ad2[d] = pd; }
}

// ---------------------------------------------------------------------------
// Kernel 5: layer-2 aggregation + fused output head
// ---------------------------------------------------------------------------
__global__ void __launch_bounds__(AGG_WARPS * 32)
agg_out_kernel(const float* __restrict__ Wout, const float* __restrict__ bout,
               const float* __restrict__ b, float* __restrict__ out, int n)
{
    __shared__ float Ws[HID * HID];
    __shared__ float bos[HID], bs[HID];
    __shared__ float hx[AGG_WARPS][HID];
    int t = threadIdx.x;
    if (t < HID * HID) Ws[t] = Wout[t];
    if (t < HID) { bos[t] = bout[t]; bs[t] = b[t]; }
    __syncthreads();

    int w = t >> 5;
    int d = blockIdx.x * AGG_WARPS + w;
    if (d >= n) return;
    int lane = t & 31;
    int c    = lane & 15;

    float4 facc; float zacc;
    agg_core(d, lane, g_h2, g_as2, __ldg(&g_ad2[d]), facc, zacc);

    if (lane < 4) *(float4*)&hx[w][lane << 2] = facc;
    __syncwarp();
    float hin = fmaxf(fmaf(hx[w][c], 1.f / (zacc + 1e-16f), bs[c]), 0.f);

    float l = bos[c];
#pragma unroll
    for (int cc = 0; cc < HID; cc++) {
        float v = __shfl_sync(0xffffffffu, hin, cc);
        l = fmaf(v, Ws[cc * HID + c], l);
    }
    float m = l;
#pragma unroll
    for (int ofs = 8; ofs > 0; ofs >>= 1)
        m = fmaxf(m, __shfl_xor_sync(0xffffffffu, m, ofs));
    float e = __expf(l - m);
    float ssum = e;
#pragma unroll
    for (int ofs = 8; ofs > 0; ofs >>= 1)
        ssum += __shfl_xor_sync(0xffffffffu, ssum, ofs);

    if (lane < HID) out[(size_t)d * HID + lane] = e / ssum;
}

// ---------------------------------------------------------------------------
extern "C" void kernel_launch(void* const* d_in, const int* in_sizes, int n_in,
                              void* d_out, int out_size)
{
    const float* x    = (const float*)d_in[0];
    const float* W1   = (const float*)d_in[1];
    const float* as1  = (const float*)d_in[2];
    const float* ad1  = (const float*)d_in[3];
    const float* b1   = (const float*)d_in[4];
    const float* W2   = (const float*)d_in[5];
    const float* as2  = (const float*)d_in[6];
    const float* ad2  = (const float*)d_in[7];
    const float* b2   = (const float*)d_in[8];
    const float* Wout = (const float*)d_in[9];
    const float* bout = (const float*)d_in[10];
    const int*   ei   = (const int*)d_in[11];

    int n = in_sizes[0] / IN_DIM;
    int E = in_sizes[11] / 2;
    float* out = (float*)d_out;

    int n1Blocks   = (n + N1T - 1) / N1T;
    int edgeBlocks = (E + 255) / 256;
    int aggBlocks  = (n + AGG_WARPS - 1) / AGG_WARPS;
    size_t smBytes = SMF_TOT * sizeof(float);

    cudaFuncSetAttribute(node1_hist_kernel,
                         cudaFuncAttributeMaxDynamicSharedMemorySize,
                         (int)smBytes);

    node1_hist_kernel<<<n1Blocks, N1T, smBytes>>>(x, W1, as1, ad1, ei, n, E);
    scan_one_kernel<<<1, 1024>>>(n, E);
    scatter_kernel<<<edgeBlocks, 256>>>(ei, E);
    agg_mid_kernel<<<aggBlocks, AGG_WARPS * 32>>>(W2, as2, ad2, b1, n);
    agg_out_kernel<<<aggBlocks, AGG_WARPS * 32>>>(Wout, bout, b2, out, n);
}

// round 7
// speedup vs baseline: 1.2812x; 1.0733x over previous
#include <cuda_runtime.h>
#include <cuda_bf16.h>

// ---------------------------------------------------------------------------
// GAT 2-layer + softmax head. 7 kernels:
//  1) node1_hist : h1 = x@W1 via cp.async double-buffered smem pipeline
//                  (128-node chunks, grid-stride), alphas, fused histogram
//  2) scan_one   : single-block int4 scan of degrees -> g_off/g_cur
//  3) scatter    : CSR column build (int4-vectorized)
//  4) agg(0)     : warp-per-dst softmax-agg -> g_acc, g_z  (layer 1)
//  5) node_mid   : relu(acc/z+b1) @ W2, new alphas -> g_h2/g_as2/g_ad2
//  6) agg(1)     : same on layer 2 -> g_acc, g_z
//  7) node_out   : relu(acc/z+b2) @ Wout + bout, softmax -> out
// ---------------------------------------------------------------------------

#define NMAX   100000
#define EMAX   3400000
#define IN_DIM 512
#define HID    16

__device__ __align__(16) float g_h  [NMAX * HID];
__device__ __align__(16) float g_h2 [NMAX * HID];
__device__ __align__(16) float g_acc[NMAX * HID];
__device__ float g_as [NMAX];
__device__ float g_ad [NMAX];
__device__ float g_as2[NMAX];
__device__ float g_ad2[NMAX];
__device__ float g_z  [NMAX];

__device__ __align__(16) int g_deg[NMAX];      // static-zero; re-zeroed by scan
__device__ __align__(16) int g_off[NMAX + 4];
__device__ __align__(16) int g_cur[NMAX];
__device__ int g_csr[EMAX];

// ---------------------------------------------------------------------------
// packed fp32x2 helpers (sm_100+)
__device__ __forceinline__ unsigned long long dup2(float v) {
    unsigned long long r;
    asm("mov.b64 %0, {%1, %1};" : "=l"(r) : "f"(v));
    return r;
}
__device__ __forceinline__ void fma2(unsigned long long& d,
                                     unsigned long long a, unsigned long long b) {
    asm("fma.rn.f32x2 %0, %1, %2, %0;" : "+l"(d) : "l"(a), "l"(b));
}
__device__ __forceinline__ float2 unpk(unsigned long long v) {
    float2 r;
    asm("mov.b64 {%0, %1}, %2;" : "=f"(r.x), "=f"(r.y) : "l"(v));
    return r;
}

// cp.async helpers
__device__ __forceinline__ void cp_async16(unsigned sm_addr, const void* g) {
    asm volatile("cp.async.cg.shared.global [%0], [%1], 16;"
                 :: "r"(sm_addr), "l"(g));
}
__device__ __forceinline__ void cp_commit() {
    asm volatile("cp.async.commit_group;");
}
__device__ __forceinline__ void cp_wait1() {
    asm volatile("cp.async.wait_group 1;");
}
__device__ __forceinline__ void cp_wait0() {
    asm volatile("cp.async.wait_group 0;");
}

// ---------------------------------------------------------------------------
// Kernel 1: node transform layer 1 (cp.async pipeline, grid-stride chunks of
// 128 nodes) + fused histogram.
// smem (floats): [W1: 8192][avs 16][avd 16][xs: 2 x 128 x 32 swizzled]
// ---------------------------------------------------------------------------
#define N1T   128
#define KT    32
#define NTILE (IN_DIM / KT)          // 16
#define SMF_W   0
#define SMF_AVS 8192
#define SMF_AVD 8208
#define SMF_XS  8224
#define SMF_TOT (SMF_XS + 2 * N1T * KT)   // 16416 floats = 65664 B

__global__ void __launch_bounds__(N1T)
node1_hist_kernel(const float* __restrict__ x, const float* __restrict__ W1,
                  const float* __restrict__ a_s, const float* __restrict__ a_d,
                  const int* __restrict__ ei, int n, int E, int nChunks)
{
    extern __shared__ float sm[];
    const int t = threadIdx.x;
    const unsigned smBase = (unsigned)__cvta_generic_to_shared(sm);

    // stage W1 + alphas once per block
    for (int j = t; j < IN_DIM * HID / 4; j += N1T)
        ((float4*)(sm + SMF_W))[j] = ((const float4*)W1)[j];
    if (t < HID)            sm[SMF_AVS + t] = a_s[t];
    else if (t < 2 * HID)   sm[SMF_AVD + t - HID] = a_d[t - HID];
    __syncthreads();

#define PREFETCH(kb, b) do {                                                  \
        int _kb = (kb);                                                       \
        unsigned _dstBase = smBase + (SMF_XS + (b) * N1T * KT) * 4;           \
        _Pragma("unroll")                                                     \
        for (int _i = 0; _i < 8; _i++) {                                      \
            int _idx = t + N1T * _i;          /* 0..1023 */                   \
            int _row = _idx >> 3;                                             \
            int _c   = _idx & 7;                                              \
            int _nd  = node0 + _row;                                          \
            if (_nd < n) {                                                    \
                unsigned _dst = _dstBase + _row * 128 +                       \
                                (((_c ^ (_row & 7))) << 4);                   \
                cp_async16(_dst, x + (size_t)_nd * IN_DIM + _kb * KT + _c*4); \
            }                                                                 \
        }                                                                     \
        cp_commit();                                                          \
    } while (0)

#pragma unroll 1
    for (int chunk = blockIdx.x; chunk < nChunks; chunk += gridDim.x) {
        const int node0 = chunk * N1T;

        unsigned long long acc[8];
#pragma unroll
        for (int p = 0; p < 8; p++) acc[p] = 0ull;

        PREFETCH(0, 0);
        PREFETCH(1, 1);

#pragma unroll 1
        for (int kb = 0; kb < NTILE; kb++) {
            if (kb == NTILE - 1) cp_wait0(); else cp_wait1();
            __syncthreads();

            const int b = kb & 1;
            const float* xbuf = sm + SMF_XS + b * N1T * KT;
            float4 xr[8];
#pragma unroll
            for (int c = 0; c < 8; c++)
                xr[c] = *(const float4*)(xbuf + t * KT + ((c ^ (t & 7)) << 2));

            __syncthreads();                 // buffer free for next prefetch
            if (kb + 2 < NTILE) PREFETCH(kb + 2, b);

#pragma unroll
            for (int c = 0; c < 8; c++) {
                float xv[4] = {xr[c].x, xr[c].y, xr[c].z, xr[c].w};
#pragma unroll
                for (int j = 0; j < 4; j++) {
                    int k = kb * KT + c * 4 + j;
                    const ulonglong2* wq =
                        (const ulonglong2*)(sm + SMF_W + k * HID);
                    ulonglong2 wa = wq[0];
                    ulonglong2 wb = wq[1];
                    unsigned long long xd = dup2(xv[j]);
                    fma2(acc[0], xd, wa.x);
                    fma2(acc[1], xd, wa.y);
                    fma2(acc[2], xd, wb.x);
                    fma2(acc[3], xd, wb.y);
                    const ulonglong2* wq2 =
                        (const ulonglong2*)(sm + SMF_W + k * HID + 8);
                    ulonglong2 wc = wq2[0];
                    ulonglong2 wd = wq2[1];
                    fma2(acc[4], xd, wc.x);
                    fma2(acc[5], xd, wc.y);
                    fma2(acc[6], xd, wd.x);
                    fma2(acc[7], xd, wd.y);
                }
            }
        }

        const int node = node0 + t;
        if (node < n) {
            float h[HID];
#pragma unroll
            for (int p = 0; p < 8; p++) {
                float2 f = unpk(acc[p]);
                h[2 * p] = f.x; h[2 * p + 1] = f.y;
            }
            float as_v = 0.f, ad_v = 0.f;
#pragma unroll
            for (int c = 0; c < HID; c++) {
                as_v = fmaf(h[c], sm[SMF_AVS + c], as_v);
                ad_v = fmaf(h[c], sm[SMF_AVD + c], ad_v);
            }
            float4* hp = (float4*)(g_h + (size_t)node * HID);
            hp[0] = make_float4(h[0],  h[1],  h[2],  h[3]);
            hp[1] = make_float4(h[4],  h[5],  h[6],  h[7]);
            hp[2] = make_float4(h[8],  h[9],  h[10], h[11]);
            hp[3] = make_float4(h[12], h[13], h[14], h[15]);
            g_as[node] = as_v;
            g_ad[node] = ad_v;
        }
    }
#undef PREFETCH

    // fused histogram (g_deg zero on entry; re-zeroed by scan)
    int gtid   = blockIdx.x * N1T + t;
    int stride = gridDim.x * N1T;
    for (int i = gtid; i < E; i += stride)
        atomicAdd(&g_deg[ei[E + i]], 1);
}

// ---------------------------------------------------------------------------
// Kernel 2: single-block scan. 1024 threads, int4 per thread per tile.
// ---------------------------------------------------------------------------
__global__ void __launch_bounds__(1024)
scan_one_kernel(int n, int E)
{
    __shared__ int wsum[32];
    __shared__ int sTot;
    const int t = threadIdx.x;
    const int lane = t & 31, wid = t >> 5;

    int running = 0;
    int nTiles = (n + 4095) >> 12;

    for (int tile = 0; tile < nTiles; tile++) {
        int base = (tile << 12) + t * 4;
        int4 v = make_int4(0, 0, 0, 0);
        if (base + 3 < n)      v = *(const int4*)(g_deg + base);
        else if (base < n) {
            v.x = g_deg[base];
            if (base + 1 < n) v.y = g_deg[base + 1];
            if (base + 2 < n) v.z = g_deg[base + 2];
        }
        int s01  = v.x + v.y;
        int tsum = s01 + v.z + v.w;

        int incl = tsum;
#pragma unroll
        for (int o = 1; o < 32; o <<= 1) {
            int u = __shfl_up_sync(0xffffffffu, incl, o);
            if (lane >= o) incl += u;
        }
        if (lane == 31) wsum[wid] = incl;
        __syncthreads();
        if (wid == 0) {
            int w = wsum[lane];
            int wi = w;
#pragma unroll
            for (int o = 1; o < 32; o <<= 1) {
                int u = __shfl_up_sync(0xffffffffu, wi, o);
                if (lane >= o) wi += u;
            }
            wsum[lane] = wi - w;
            if (lane == 31) sTot = wi;
        }
        __syncthreads();

        int pre = running + wsum[wid] + (incl - tsum);
        if (base + 3 < n) {
            int4 o4 = make_int4(pre, pre + v.x, pre + s01, pre + s01 + v.z);
            *(int4*)(g_off + base) = o4;
            *(int4*)(g_cur + base) = o4;
            *(int4*)(g_deg + base) = make_int4(0, 0, 0, 0);
        } else if (base < n) {
            int o0 = pre, o1 = pre + v.x, o2 = pre + s01;
            g_off[base] = o0; g_cur[base] = o0; g_deg[base] = 0;
            if (base + 1 < n) { g_off[base+1] = o1; g_cur[base+1] = o1; g_deg[base+1] = 0; }
            if (base + 2 < n) { g_off[base+2] = o2; g_cur[base+2] = o2; g_deg[base+2] = 0; }
        }
        running += sTot;
        __syncthreads();
    }
    if (t == 0) g_off[n] = E;
}

// ---------------------------------------------------------------------------
// Kernel 3: CSR scatter. Vectorized (4 edges/thread) when E % 4 == 0.
// ---------------------------------------------------------------------------
__global__ void __launch_bounds__(256)
scatter4_kernel(const int* __restrict__ ei, int E)
{
    int i = (blockIdx.x * blockDim.x + threadIdx.x) << 2;
    if (i >= E) return;
    int4 s4 = *(const int4*)(ei + i);
    int4 d4 = *(const int4*)(ei + E + i);
    g_csr[atomicAdd(&g_cur[d4.x], 1)] = s4.x;
    g_csr[atomicAdd(&g_cur[d4.y], 1)] = s4.y;
    g_csr[atomicAdd(&g_cur[d4.z], 1)] = s4.z;
    g_csr[atomicAdd(&g_cur[d4.w], 1)] = s4.w;
}

__global__ void __launch_bounds__(256)
scatter_kernel(const int* __restrict__ ei, int E)
{
    int i = blockIdx.x * blockDim.x + threadIdx.x;
    if (i < E) {
        int d = __ldg(ei + E + i);
        int pos = atomicAdd(&g_cur[d], 1);
        g_csr[pos] = __ldg(ei + i);
    }
}

// ---------------------------------------------------------------------------
// Kernel 4/6: pure warp-per-dst aggregation (8 edge-slots x 4-feature quads).
// layer=0: g_h/g_as/g_ad ; layer=1: g_h2/g_as2/g_ad2.  Writes g_acc, g_z.
// ---------------------------------------------------------------------------
#define AGG_WARPS 8

__global__ void __launch_bounds__(AGG_WARPS * 32)
agg_kernel(int layer, int n)
{
    const float* __restrict__ hsrc = layer ? g_h2  : g_h;
    const float* __restrict__ asrc = layer ? g_as2 : g_as;
    const float* __restrict__ adrc = layer ? g_ad2 : g_ad;

    int d = blockIdx.x * AGG_WARPS + (threadIdx.x >> 5);
    if (d >= n) return;
    const int lane = threadIdx.x & 31;
    const int slot = lane >> 2;
    const int coff = (lane & 3) << 2;

    const int begin = g_off[d];
    const int deg   = g_off[d + 1] - begin;
    const int nE    = deg + 1;
    const float ad_d = __ldg(adrc + d);

    float4 facc = make_float4(0.f, 0.f, 0.f, 0.f);
    float  zacc = 0.f;

    const int fullB = nE >> 5;
    for (int b = 0; b < fullB; b++) {
        int eidx = (b << 5) + lane;
        int s = (eidx < deg) ? __ldg(g_csr + begin + eidx) : d;
        float v = __ldg(asrc + s) + ad_d;
        v = (v > 0.f) ? v : 0.2f * v;
        float e = __expf(v);
        zacc += e;
#pragma unroll
        for (int j = 0; j < 4; j++) {
            int   sl = (j << 3) + slot;
            float e2 = __shfl_sync(0xffffffffu, e, sl);
            int   s2 = __shfl_sync(0xffffffffu, s, sl);
            float4 hv = *(const float4*)(hsrc + s2 * HID + coff);
            facc.x = fmaf(e2, hv.x, facc.x);
            facc.y = fmaf(e2, hv.y, facc.y);
            facc.z = fmaf(e2, hv.z, facc.z);
            facc.w = fmaf(e2, hv.w, facc.w);
        }
    }
    int b0 = fullB << 5;
    if (b0 < nE) {
        int eidx = b0 + lane;
        bool valid = eidx < nE;
        int s = (eidx < deg) ? __ldg(g_csr + begin + eidx) : d;
        float v = __ldg(asrc + s) + ad_d;
        v = (v > 0.f) ? v : 0.2f * v;
        float e = valid ? __expf(v) : 0.f;
        zacc += e;
        int jmax = (nE - b0 + 7) >> 3;
#pragma unroll 4
        for (int j = 0; j < jmax; j++) {
            int   sl = (j << 3) + slot;
            float e2 = __shfl_sync(0xffffffffu, e, sl);
            int   s2 = __shfl_sync(0xffffffffu, s, sl);
            float4 hv = *(const float4*)(hsrc + s2 * HID + coff);
            facc.x = fmaf(e2, hv.x, facc.x);
            facc.y = fmaf(e2, hv.y, facc.y);
            facc.z = fmaf(e2, hv.z, facc.z);
            facc.w = fmaf(e2, hv.w, facc.w);
        }
    }

    // reduce over slots (lane bits 2..4); z to lane 0
#pragma unroll
    for (int m = 4; m <= 16; m <<= 1) {
        facc.x += __shfl_xor_sync(0xffffffffu, facc.x, m);
        facc.y += __shfl_xor_sync(0xffffffffu, facc.y, m);
        facc.z += __shfl_xor_sync(0xffffffffu, facc.z, m);
        facc.w += __shfl_xor_sync(0xffffffffu, facc.w, m);
    }
#pragma unroll
    for (int m = 16; m > 0; m >>= 1)
        zacc += __shfl_xor_sync(0xffffffffu, zacc, m);

    if (lane < 4)
        *(float4*)(g_acc + (size_t)d * HID + coff) = facc;
    if (lane == 0)
        g_z[d] = zacc;
}

// ---------------------------------------------------------------------------
// Kernel 5: node-mid — relu(acc/z+b1) @ W2, new alphas -> g_h2/g_as2/g_ad2
// ---------------------------------------------------------------------------
__global__ void __launch_bounds__(256)
node_mid_kernel(const float* __restrict__ W2, const float* __restrict__ a_s,
                const float* __restrict__ a_d, const float* __restrict__ b,
                int n)
{
    __shared__ float Ws[HID * HID];
    __shared__ float avs[HID], avd[HID], bs[HID];
    const int t = threadIdx.x;
    if (t < HID * HID) Ws[t] = W2[t];
    if (t < HID) { avs[t] = a_s[t]; avd[t] = a_d[t]; bs[t] = b[t]; }
    __syncthreads();

    int i = blockIdx.x * blockDim.x + t;
    if (i >= n) return;

    float inv = 1.f / (g_z[i] + 1e-16f);
    const float4* ap = (const float4*)(g_acc + (size_t)i * HID);
    float4 a0 = ap[0], a1 = ap[1], a2 = ap[2], a3 = ap[3];
    float hin[HID] = {a0.x, a0.y, a0.z, a0.w, a1.x, a1.y, a1.z, a1.w,
                      a2.x, a2.y, a2.z, a2.w, a3.x, a3.y, a3.z, a3.w};
#pragma unroll
    for (int c = 0; c < HID; c++)
        hin[c] = fmaxf(fmaf(hin[c], inv, bs[c]), 0.f);

    float h2[HID];
#pragma unroll
    for (int j = 0; j < HID; j++) h2[j] = 0.f;
#pragma unroll
    for (int c = 0; c < HID; c++) {
        float v = hin[c];
#pragma unroll
        for (int j = 0; j < HID; j++)
            h2[j] = fmaf(v, Ws[c * HID + j], h2[j]);
    }

    float as_v = 0.f, ad_v = 0.f;
#pragma unroll
    for (int c = 0; c < HID; c++) {
        as_v = fmaf(h2[c], avs[c], as_v);
        ad_v = fmaf(h2[c], avd[c], ad_v);
    }

    float4* hp = (float4*)(g_h2 + (size_t)i * HID);
    hp[0] = make_float4(h2[0],  h2[1],  h2[2],  h2[3]);
    hp[1] = make_float4(h2[4],  h2[5],  h2[6],  h2[7]);
    hp[2] = make_float4(h2[8],  h2[9],  h2[10], h2[11]);
    hp[3] = make_float4(h2[12], h2[13], h2[14], h2[15]);
    g_as2[i] = as_v;
    g_ad2[i] = ad_v;
}

// ---------------------------------------------------------------------------
// Kernel 7: node-out — relu(acc/z+b2) @ Wout + bout, softmax -> out
// ---------------------------------------------------------------------------
__global__ void __launch_bounds__(256)
node_out_kernel(const float* __restrict__ Wout, const float* __restrict__ bout,
                const float* __restrict__ b, float* __restrict__ out, int n)
{
    __shared__ float Ws[HID * HID];
    __shared__ float bos[HID], bs[HID];
    const int t = threadIdx.x;
    if (t < HID * HID) Ws[t] = Wout[t];
    if (t < HID) { bos[t] = bout[t]; bs[t] = b[t]; }
    __syncthreads();

    int i = blockIdx.x * blockDim.x + t;
    if (i >= n) return;

    float inv = 1.f / (g_z[i] + 1e-16f);
    const float4* ap = (const float4*)(g_acc + (size_t)i * HID);
    float4 a0 = ap[0], a1 = ap[1], a2 = ap[2], a3 = ap[3];
    float hin[HID] = {a0.x, a0.y, a0.z, a0.w, a1.x, a1.y, a1.z, a1.w,
                      a2.x, a2.y, a2.z, a2.w, a3.x, a3.y, a3.z, a3.w};
#pragma unroll
    for (int c = 0; c < HID; c++)
        hin[c] = fmaxf(fmaf(hin[c], inv, bs[c]), 0.f);

    float l[HID];
#pragma unroll
    for (int j = 0; j < HID; j++) l[j] = bos[j];
#pragma unroll
    for (int c = 0; c < HID; c++) {
        float v = hin[c];
#pragma unroll
        for (int j = 0; j < HID; j++)
            l[j] = fmaf(v, Ws[c * HID + j], l[j]);
    }

    float m = l[0];
#pragma unroll
    for (int j = 1; j < HID; j++) m = fmaxf(m, l[j]);
    float ssum = 0.f;
#pragma unroll
    for (int j = 0; j < HID; j++) { l[j] = __expf(l[j] - m); ssum += l[j]; }
    float sinv = 1.f / ssum;

    float4* op = (float4*)(out + (size_t)i * HID);
    op[0] = make_float4(l[0]  * sinv, l[1]  * sinv, l[2]  * sinv, l[3]  * sinv);
    op[1] = make_float4(l[4]  * sinv, l[5]  * sinv, l[6]  * sinv, l[7]  * sinv);
    op[2] = make_float4(l[8]  * sinv, l[9]  * sinv, l[10] * sinv, l[11] * sinv);
    op[3] = make_float4(l[12] * sinv, l[13] * sinv, l[14] * sinv, l[15] * sinv);
}

// ---------------------------------------------------------------------------
extern "C" void kernel_launch(void* const* d_in, const int* in_sizes, int n_in,
                              void* d_out, int out_size)
{
    const float* x    = (const float*)d_in[0];
    const float* W1   = (const float*)d_in[1];
    const float* as1  = (const float*)d_in[2];
    const float* ad1  = (const float*)d_in[3];
    const float* b1   = (const float*)d_in[4];
    const float* W2   = (const float*)d_in[5];
    const float* as2  = (const float*)d_in[6];
    const float* ad2  = (const float*)d_in[7];
    const float* b2   = (const float*)d_in[8];
    const float* Wout = (const float*)d_in[9];
    const float* bout = (const float*)d_in[10];
    const int*   ei   = (const int*)d_in[11];

    int n = in_sizes[0] / IN_DIM;
    int E = in_sizes[11] / 2;
    float* out = (float*)d_out;

    int nChunks  = (n + N1T - 1) / N1T;
    int n1Blocks = nChunks < 444 ? nChunks : 444;
    int nodeBlocks = (n + 255) / 256;
    int aggBlocks  = (n + AGG_WARPS - 1) / AGG_WARPS;
    size_t smBytes = SMF_TOT * sizeof(float);

    cudaFuncSetAttribute(node1_hist_kernel,
                         cudaFuncAttributeMaxDynamicSharedMemorySize,
                         (int)smBytes);

    node1_hist_kernel<<<n1Blocks, N1T, smBytes>>>(x, W1, as1, ad1, ei, n, E,
                                                  nChunks);
    scan_one_kernel<<<1, 1024>>>(n, E);
    if ((E & 3) == 0)
        scatter4_kernel<<<(E / 4 + 255) / 256, 256>>>(ei, E);
    else
        scatter_kernel<<<(E + 255) / 256, 256>>>(ei, E);
    agg_kernel<<<aggBlocks, AGG_WARPS * 32>>>(0, n);
    node_mid_kernel<<<nodeBlocks, 256>>>(W2, as2, ad2, b1, n);
    agg_kernel<<<aggBlocks, AGG_WARPS * 32>>>(1, n);
    node_out_kernel<<<nodeBlocks, 256>>>(Wout, bout, b2, out, n);
}

// round 8
// speedup vs baseline: 1.3290x; 1.0373x over previous
#include <cuda_runtime.h>
#include <cuda_bf16.h>

// ---------------------------------------------------------------------------
// GAT 2-layer + softmax head. Forked-stream schedule:
//   side stream : hist4 -> scan_one -> scatter4     (CSR build, ~50us)
//   main stream : node1 (x@W1, cp.async pipeline)   (~90us)   [overlapped]
//   join        : agg(0) -> node_mid -> agg(1) -> node_out
// ---------------------------------------------------------------------------

#define NMAX   100000
#define EMAX   3400000
#define IN_DIM 512
#define HID    16

__device__ __align__(16) float g_h  [NMAX * HID];
__device__ __align__(16) float g_h2 [NMAX * HID];
__device__ __align__(16) float g_acc[NMAX * HID];
__device__ float g_as [NMAX];
__device__ float g_ad [NMAX];
__device__ float g_as2[NMAX];
__device__ float g_ad2[NMAX];
__device__ float g_z  [NMAX];

__device__ __align__(16) int g_deg[NMAX];      // static-zero; re-zeroed by scan
__device__ __align__(16) int g_off[NMAX + 4];
__device__ __align__(16) int g_cur[NMAX];
__device__ int g_csr[EMAX];
__device__ int g_chunk;                        // node1 work counter (reset by node_out)

// ---------------------------------------------------------------------------
// packed fp32x2 helpers (sm_100+)
__device__ __forceinline__ unsigned long long dup2(float v) {
    unsigned long long r;
    asm("mov.b64 %0, {%1, %1};" : "=l"(r) : "f"(v));
    return r;
}
__device__ __forceinline__ void fma2(unsigned long long& d,
                                     unsigned long long a, unsigned long long b) {
    asm("fma.rn.f32x2 %0, %1, %2, %0;" : "+l"(d) : "l"(a), "l"(b));
}
__device__ __forceinline__ float2 unpk(unsigned long long v) {
    float2 r;
    asm("mov.b64 {%0, %1}, %2;" : "=f"(r.x), "=f"(r.y) : "l"(v));
    return r;
}

// cp.async helpers
__device__ __forceinline__ void cp_async16(unsigned sm_addr, const void* g) {
    asm volatile("cp.async.cg.shared.global [%0], [%1], 16;"
                 :: "r"(sm_addr), "l"(g));
}
__device__ __forceinline__ void cp_commit() {
    asm volatile("cp.async.commit_group;");
}
__device__ __forceinline__ void cp_wait1() {
    asm volatile("cp.async.wait_group 1;");
}
__device__ __forceinline__ void cp_wait0() {
    asm volatile("cp.async.wait_group 0;");
}

// ---------------------------------------------------------------------------
// Kernel 1 (main stream): x@W1 via cp.async double-buffered pipeline.
// Dynamic chunk scheduling via g_chunk. 128 nodes per chunk.
// ---------------------------------------------------------------------------
#define N1T   128
#define KT    32
#define NTILE (IN_DIM / KT)          // 16
#define SMF_W   0
#define SMF_AVS 8192
#define SMF_AVD 8208
#define SMF_XS  8224
#define SMF_TOT (SMF_XS + 2 * N1T * KT)   // 16416 floats = 65664 B

__global__ void __launch_bounds__(N1T)
node1_kernel(const float* __restrict__ x, const float* __restrict__ W1,
             const float* __restrict__ a_s, const float* __restrict__ a_d,
             int n, int nChunks)
{
    extern __shared__ float sm[];
    const int t = threadIdx.x;
    const unsigned smBase = (unsigned)__cvta_generic_to_shared(sm);

    for (int j = t; j < IN_DIM * HID / 4; j += N1T)
        ((float4*)(sm + SMF_W))[j] = ((const float4*)W1)[j];
    if (t < HID)            sm[SMF_AVS + t] = a_s[t];
    else if (t < 2 * HID)   sm[SMF_AVD + t - HID] = a_d[t - HID];

    __shared__ int sChunk;

#define PREFETCH(kb, b) do {                                                  \
        int _kb = (kb);                                                       \
        unsigned _dstBase = smBase + (SMF_XS + (b) * N1T * KT) * 4;           \
        _Pragma("unroll")                                                     \
        for (int _i = 0; _i < 8; _i++) {                                      \
            int _idx = t + N1T * _i;          /* 0..1023 */                   \
            int _row = _idx >> 3;                                             \
            int _c   = _idx & 7;                                              \
            int _nd  = node0 + _row;                                          \
            if (_nd < n) {                                                    \
                unsigned _dst = _dstBase + _row * 128 +                       \
                                (((_c ^ (_row & 7))) << 4);                   \
                cp_async16(_dst, x + (size_t)_nd * IN_DIM + _kb * KT + _c*4); \
            }                                                                 \
        }                                                                     \
        cp_commit();                                                          \
    } while (0)

    while (true) {
        __syncthreads();                 // protect sChunk & W staging
        if (t == 0) sChunk = atomicAdd(&g_chunk, 1);
        __syncthreads();
        const int chunk = sChunk;
        if (chunk >= nChunks) break;
        const int node0 = chunk * N1T;

        unsigned long long acc[8];
#pragma unroll
        for (int p = 0; p < 8; p++) acc[p] = 0ull;

        PREFETCH(0, 0);
        PREFETCH(1, 1);

#pragma unroll 1
        for (int kb = 0; kb < NTILE; kb++) {
            if (kb == NTILE - 1) cp_wait0(); else cp_wait1();
            __syncthreads();

            const int b = kb & 1;
            const float* xbuf = sm + SMF_XS + b * N1T * KT;
            float4 xr[8];
#pragma unroll
            for (int c = 0; c < 8; c++)
                xr[c] = *(const float4*)(xbuf + t * KT + ((c ^ (t & 7)) << 2));

            __syncthreads();             // buffer free for next prefetch
            if (kb + 2 < NTILE) PREFETCH(kb + 2, b);

#pragma unroll
            for (int c = 0; c < 8; c++) {
                float xv[4] = {xr[c].x, xr[c].y, xr[c].z, xr[c].w};
#pragma unroll
                for (int j = 0; j < 4; j++) {
                    int k = kb * KT + c * 4 + j;
                    const ulonglong2* wq =
                        (const ulonglong2*)(sm + SMF_W + k * HID);
                    ulonglong2 wa = wq[0];
                    ulonglong2 wb = wq[1];
                    unsigned long long xd = dup2(xv[j]);
                    fma2(acc[0], xd, wa.x);
                    fma2(acc[1], xd, wa.y);
                    fma2(acc[2], xd, wb.x);
                    fma2(acc[3], xd, wb.y);
                    const ulonglong2* wq2 =
                        (const ulonglong2*)(sm + SMF_W + k * HID + 8);
                    ulonglong2 wc = wq2[0];
                    ulonglong2 wd = wq2[1];
                    fma2(acc[4], xd, wc.x);
                    fma2(acc[5], xd, wc.y);
                    fma2(acc[6], xd, wd.x);
                    fma2(acc[7], xd, wd.y);
                }
            }
        }

        const int node = node0 + t;
        if (node < n) {
            float h[HID];
#pragma unroll
            for (int p = 0; p < 8; p++) {
                float2 f = unpk(acc[p]);
                h[2 * p] = f.x; h[2 * p + 1] = f.y;
            }
            float as_v = 0.f, ad_v = 0.f;
#pragma unroll
            for (int c = 0; c < HID; c++) {
                as_v = fmaf(h[c], sm[SMF_AVS + c], as_v);
                ad_v = fmaf(h[c], sm[SMF_AVD + c], ad_v);
            }
            float4* hp = (float4*)(g_h + (size_t)node * HID);
            hp[0] = make_float4(h[0],  h[1],  h[2],  h[3]);
            hp[1] = make_float4(h[4],  h[5],  h[6],  h[7]);
            hp[2] = make_float4(h[8],  h[9],  h[10], h[11]);
            hp[3] = make_float4(h[12], h[13], h[14], h[15]);
            g_as[node] = as_v;
            g_ad[node] = ad_v;
        }
    }
#undef PREFETCH
}

// ---------------------------------------------------------------------------
// Side-stream kernel A: histogram (int4-vectorized).
// ---------------------------------------------------------------------------
__global__ void __launch_bounds__(256)
hist4_kernel(const int* __restrict__ ei, int E)
{
    int i = (blockIdx.x * blockDim.x + threadIdx.x) << 2;
    if (i + 3 < E) {
        int4 d4 = *(const int4*)(ei + E + i);
        atomicAdd(&g_deg[d4.x], 1);
        atomicAdd(&g_deg[d4.y], 1);
        atomicAdd(&g_deg[d4.z], 1);
        atomicAdd(&g_deg[d4.w], 1);
    } else {
        for (int k = i; k < E; k++) atomicAdd(&g_deg[__ldg(ei + E + k)], 1);
    }
}

// ---------------------------------------------------------------------------
// Side-stream kernel B: single-block scan -> g_off/g_cur, re-zero g_deg.
// ---------------------------------------------------------------------------
__global__ void __launch_bounds__(1024)
scan_one_kernel(int n, int E)
{
    __shared__ int wsum[32];
    __shared__ int sTot;
    const int t = threadIdx.x;
    const int lane = t & 31, wid = t >> 5;

    int running = 0;
    int nTiles = (n + 4095) >> 12;

    for (int tile = 0; tile < nTiles; tile++) {
        int base = (tile << 12) + t * 4;
        int4 v = make_int4(0, 0, 0, 0);
        if (base + 3 < n)      v = *(const int4*)(g_deg + base);
        else if (base < n) {
            v.x = g_deg[base];
            if (base + 1 < n) v.y = g_deg[base + 1];
            if (base + 2 < n) v.z = g_deg[base + 2];
        }
        int s01  = v.x + v.y;
        int tsum = s01 + v.z + v.w;

        int incl = tsum;
#pragma unroll
        for (int o = 1; o < 32; o <<= 1) {
            int u = __shfl_up_sync(0xffffffffu, incl, o);
            if (lane >= o) incl += u;
        }
        if (lane == 31) wsum[wid] = incl;
        __syncthreads();
        if (wid == 0) {
            int w = wsum[lane];
            int wi = w;
#pragma unroll
            for (int o = 1; o < 32; o <<= 1) {
                int u = __shfl_up_sync(0xffffffffu, wi, o);
                if (lane >= o) wi += u;
            }
            wsum[lane] = wi - w;
            if (lane == 31) sTot = wi;
        }
        __syncthreads();

        int pre = running + wsum[wid] + (incl - tsum);
        if (base + 3 < n) {
            int4 o4 = make_int4(pre, pre + v.x, pre + s01, pre + s01 + v.z);
            *(int4*)(g_off + base) = o4;
            *(int4*)(g_cur + base) = o4;
            *(int4*)(g_deg + base) = make_int4(0, 0, 0, 0);
        } else if (base < n) {
            int o0 = pre, o1 = pre + v.x, o2 = pre + s01;
            g_off[base] = o0; g_cur[base] = o0; g_deg[base] = 0;
            if (base + 1 < n) { g_off[base+1] = o1; g_cur[base+1] = o1; g_deg[base+1] = 0; }
            if (base + 2 < n) { g_off[base+2] = o2; g_cur[base+2] = o2; g_deg[base+2] = 0; }
        }
        running += sTot;
        __syncthreads();
    }
    if (t == 0) g_off[n] = E;
}

// ---------------------------------------------------------------------------
// Side-stream kernel C: CSR scatter (int4-vectorized).
// ---------------------------------------------------------------------------
__global__ void __launch_bounds__(256)
scatter4_kernel(const int* __restrict__ ei, int E)
{
    int i = (blockIdx.x * blockDim.x + threadIdx.x) << 2;
    if (i + 3 < E) {
        int4 s4 = *(const int4*)(ei + i);
        int4 d4 = *(const int4*)(ei + E + i);
        g_csr[atomicAdd(&g_cur[d4.x], 1)] = s4.x;
        g_csr[atomicAdd(&g_cur[d4.y], 1)] = s4.y;
        g_csr[atomicAdd(&g_cur[d4.z], 1)] = s4.z;
        g_csr[atomicAdd(&g_cur[d4.w], 1)] = s4.w;
    } else {
        for (int k = i; k < E; k++) {
            int d = __ldg(ei + E + k);
            g_csr[atomicAdd(&g_cur[d], 1)] = __ldg(ei + k);
        }
    }
}

// ---------------------------------------------------------------------------
// agg: warp-per-dst softmax aggregation (8 edge-slots x 4-feature quads).
// ---------------------------------------------------------------------------
#define AGG_WARPS 8

__global__ void __launch_bounds__(AGG_WARPS * 32, 6)
agg_kernel(int layer, int n)
{
    const float* __restrict__ hsrc = layer ? g_h2  : g_h;
    const float* __restrict__ asrc = layer ? g_as2 : g_as;
    const float* __restrict__ adrc = layer ? g_ad2 : g_ad;

    int d = blockIdx.x * AGG_WARPS + (threadIdx.x >> 5);
    if (d >= n) return;
    const int lane = threadIdx.x & 31;
    const int slot = lane >> 2;
    const int coff = (lane & 3) << 2;

    const int begin = g_off[d];
    const int deg   = g_off[d + 1] - begin;
    const int nE    = deg + 1;
    const float ad_d = __ldg(adrc + d);

    float4 facc = make_float4(0.f, 0.f, 0.f, 0.f);
    float  zacc = 0.f;

    const int fullB = nE >> 5;
    for (int b = 0; b < fullB; b++) {
        int eidx = (b << 5) + lane;
        int s = (eidx < deg) ? __ldg(g_csr + begin + eidx) : d;
        float v = __ldg(asrc + s) + ad_d;
        v = (v > 0.f) ? v : 0.2f * v;
        float e = __expf(v);
        zacc += e;
#pragma unroll
        for (int j = 0; j < 4; j++) {
            int   sl = (j << 3) + slot;
            float e2 = __shfl_sync(0xffffffffu, e, sl);
            int   s2 = __shfl_sync(0xffffffffu, s, sl);
            float4 hv = *(const float4*)(hsrc + s2 * HID + coff);
            facc.x = fmaf(e2, hv.x, facc.x);
            facc.y = fmaf(e2, hv.y, facc.y);
            facc.z = fmaf(e2, hv.z, facc.z);
            facc.w = fmaf(e2, hv.w, facc.w);
        }
    }
    int b0 = fullB << 5;
    if (b0 < nE) {
        int eidx = b0 + lane;
        bool valid = eidx < nE;
        int s = (eidx < deg) ? __ldg(g_csr + begin + eidx) : d;
        float v = __ldg(asrc + s) + ad_d;
        v = (v > 0.f) ? v : 0.2f * v;
        float e = valid ? __expf(v) : 0.f;
        zacc += e;
        int jmax = (nE - b0 + 7) >> 3;
#pragma unroll 4
        for (int j = 0; j < jmax; j++) {
            int   sl = (j << 3) + slot;
            float e2 = __shfl_sync(0xffffffffu, e, sl);
            int   s2 = __shfl_sync(0xffffffffu, s, sl);
            float4 hv = *(const float4*)(hsrc + s2 * HID + coff);
            facc.x = fmaf(e2, hv.x, facc.x);
            facc.y = fmaf(e2, hv.y, facc.y);
            facc.z = fmaf(e2, hv.z, facc.z);
            facc.w = fmaf(e2, hv.w, facc.w);
        }
    }

#pragma unroll
    for (int m = 4; m <= 16; m <<= 1) {
        facc.x += __shfl_xor_sync(0xffffffffu, facc.x, m);
        facc.y += __shfl_xor_sync(0xffffffffu, facc.y, m);
        facc.z += __shfl_xor_sync(0xffffffffu, facc.z, m);
        facc.w += __shfl_xor_sync(0xffffffffu, facc.w, m);
    }
#pragma unroll
    for (int m = 16; m > 0; m >>= 1)
        zacc += __shfl_xor_sync(0xffffffffu, zacc, m);

    if (lane < 4)
        *(float4*)(g_acc + (size_t)d * HID + coff) = facc;
    if (lane == 0)
        g_z[d] = zacc;
}

// ---------------------------------------------------------------------------
// node_mid: relu(acc/z+b1) @ W2, new alphas -> g_h2/g_as2/g_ad2
// ---------------------------------------------------------------------------
__global__ void __launch_bounds__(256)
node_mid_kernel(const float* __restrict__ W2, const float* __restrict__ a_s,
                const float* __restrict__ a_d, const float* __restrict__ b,
                int n)
{
    __shared__ float Ws[HID * HID];
    __shared__ float avs[HID], avd[HID], bs[HID];
    const int t = threadIdx.x;
    if (t < HID * HID) Ws[t] = W2[t];
    if (t < HID) { avs[t] = a_s[t]; avd[t] = a_d[t]; bs[t] = b[t]; }
    __syncthreads();

    int i = blockIdx.x * blockDim.x + t;
    if (i >= n) return;

    float inv = 1.f / (g_z[i] + 1e-16f);
    const float4* ap = (const float4*)(g_acc + (size_t)i * HID);
    float4 a0 = ap[0], a1 = ap[1], a2 = ap[2], a3 = ap[3];
    float hin[HID] = {a0.x, a0.y, a0.z, a0.w, a1.x, a1.y, a1.z, a1.w,
                      a2.x, a2.y, a2.z, a2.w, a3.x, a3.y, a3.z, a3.w};
#pragma unroll
    for (int c = 0; c < HID; c++)
        hin[c] = fmaxf(fmaf(hin[c], inv, bs[c]), 0.f);

    float h2[HID];
#pragma unroll
    for (int j = 0; j < HID; j++) h2[j] = 0.f;
#pragma unroll
    for (int c = 0; c < HID; c++) {
        float v = hin[c];
#pragma unroll
        for (int j = 0; j < HID; j++)
            h2[j] = fmaf(v, Ws[c * HID + j], h2[j]);
    }

    float as_v = 0.f, ad_v = 0.f;
#pragma unroll
    for (int c = 0; c < HID; c++) {
        as_v = fmaf(h2[c], avs[c], as_v);
        ad_v = fmaf(h2[c], avd[c], ad_v);
    }

    float4* hp = (float4*)(g_h2 + (size_t)i * HID);
    hp[0] = make_float4(h2[0],  h2[1],  h2[2],  h2[3]);
    hp[1] = make_float4(h2[4],  h2[5],  h2[6],  h2[7]);
    hp[2] = make_float4(h2[8],  h2[9],  h2[10], h2[11]);
    hp[3] = make_float4(h2[12], h2[13], h2[14], h2[15]);
    g_as2[i] = as_v;
    g_ad2[i] = ad_v;
}

// ---------------------------------------------------------------------------
// node_out: relu(acc/z+b2) @ Wout + bout, softmax -> out. Resets g_chunk.
// ---------------------------------------------------------------------------
__global__ void __launch_bounds__(256)
node_out_kernel(const float* __restrict__ Wout, const float* __restrict__ bout,
                const float* __restrict__ b, float* __restrict__ out, int n)
{
    __shared__ float Ws[HID * HID];
    __shared__ float bos[HID], bs[HID];
    const int t = threadIdx.x;
    if (t < HID * HID) Ws[t] = Wout[t];
    if (t < HID) { bos[t] = bout[t]; bs[t] = b[t]; }
    if (blockIdx.x == 0 && t == 0) g_chunk = 0;   // ready for next replay
    __syncthreads();

    int i = blockIdx.x * blockDim.x + t;
    if (i >= n) return;

    float inv = 1.f / (g_z[i] + 1e-16f);
    const float4* ap = (const float4*)(g_acc + (size_t)i * HID);
    float4 a0 = ap[0], a1 = ap[1], a2 = ap[2], a3 = ap[3];
    float hin[HID] = {a0.x, a0.y, a0.z, a0.w, a1.x, a1.y, a1.z, a1.w,
                      a2.x, a2.y, a2.z, a2.w, a3.x, a3.y, a3.z, a3.w};
#pragma unroll
    for (int c = 0; c < HID; c++)
        hin[c] = fmaxf(fmaf(hin[c], inv, bs[c]), 0.f);

    float l[HID];
#pragma unroll
    for (int j = 0; j < HID; j++) l[j] = bos[j];
#pragma unroll
    for (int c = 0; c < HID; c++) {
        float v = hin[c];
#pragma unroll
        for (int j = 0; j < HID; j++)
            l[j] = fmaf(v, Ws[c * HID + j], l[j]);
    }

    float m = l[0];
#pragma unroll
    for (int j = 1; j < HID; j++) m = fmaxf(m, l[j]);
    float ssum = 0.f;
#pragma unroll
    for (int j = 0; j < HID; j++) { l[j] = __expf(l[j] - m); ssum += l[j]; }
    float sinv = 1.f / ssum;

    float4* op = (float4*)(out + (size_t)i * HID);
    op[0] = make_float4(l[0]  * sinv, l[1]  * sinv, l[2]  * sinv, l[3]  * sinv);
    op[1] = make_float4(l[4]  * sinv, l[5]  * sinv, l[6]  * sinv, l[7]  * sinv);
    op[2] = make_float4(l[8]  * sinv, l[9]  * sinv, l[10] * sinv, l[11] * sinv);
    op[3] = make_float4(l[12] * sinv, l[13] * sinv, l[14] * sinv, l[15] * sinv);
}

// ---------------------------------------------------------------------------
// Host-side stream/event resources (created once at static init; host objects)
// ---------------------------------------------------------------------------
static cudaStream_t g_side = nullptr;
static cudaEvent_t  g_evFork = nullptr;
static cudaEvent_t  g_evJoin = nullptr;

static struct _ResInit {
    _ResInit() {
        cudaStreamCreateWithFlags(&g_side, cudaStreamNonBlocking);
        cudaEventCreateWithFlags(&g_evFork, cudaEventDisableTiming);
        cudaEventCreateWithFlags(&g_evJoin, cudaEventDisableTiming);
    }
} _resInit;

// ---------------------------------------------------------------------------
extern "C" void kernel_launch(void* const* d_in, const int* in_sizes, int n_in,
                              void* d_out, int out_size)
{
    const float* x    = (const float*)d_in[0];
    const float* W1   = (const float*)d_in[1];
    const float* as1  = (const float*)d_in[2];
    const float* ad1  = (const float*)d_in[3];
    const float* b1   = (const float*)d_in[4];
    const float* W2   = (const float*)d_in[5];
    const float* as2  = (const float*)d_in[6];
    const float* ad2  = (const float*)d_in[7];
    const float* b2   = (const float*)d_in[8];
    const float* Wout = (const float*)d_in[9];
    const float* bout = (const float*)d_in[10];
    const int*   ei   = (const int*)d_in[11];

    int n = in_sizes[0] / IN_DIM;
    int E = in_sizes[11] / 2;
    float* out = (float*)d_out;

    int nChunks  = (n + N1T - 1) / N1T;
    int n1Blocks = nChunks < 444 ? nChunks : 444;
    int nodeBlocks = (n + 255) / 256;
    int aggBlocks  = (n + AGG_WARPS - 1) / AGG_WARPS;
    int e4Blocks   = (E / 4 + 255) / 256;
    size_t smBytes = SMF_TOT * sizeof(float);

    cudaFuncSetAttribute(node1_kernel,
                         cudaFuncAttributeMaxDynamicSharedMemorySize,
                         (int)smBytes);

    // fork: side stream builds CSR while main stream runs node1
    cudaEventRecord(g_evFork, 0);
    cudaStreamWaitEvent(g_side, g_evFork, 0);

    hist4_kernel<<<e4Blocks, 256, 0, g_side>>>(ei, E);
    scan_one_kernel<<<1, 1024, 0, g_side>>>(n, E);
    scatter4_kernel<<<e4Blocks, 256, 0, g_side>>>(ei, E);

    node1_kernel<<<n1Blocks, N1T, smBytes>>>(x, W1, as1, ad1, n, nChunks);

    // join
    cudaEventRecord(g_evJoin, g_side);
    cudaStreamWaitEvent(0, g_evJoin, 0);

    agg_kernel<<<aggBlocks, AGG_WARPS * 32>>>(0, n);
    node_mid_kernel<<<nodeBlocks, 256>>>(W2, as2, ad2, b1, n);
    agg_kernel<<<aggBlocks, AGG_WARPS * 32>>>(1, n);
    node_out_kernel<<<nodeBlocks, 256>>>(Wout, bout, b2, out, n);
}